// round 9
// baseline (speedup 1.0000x reference)
#include <cuda_runtime.h>

#define N_PTS   131072
#define K_CB    1024
#define NPAIR   512          // K_CB / 2
#define D_DIM   10
#define PROW    20           // floats per code-pair row: 10 dims x f32x2
#define THREADS 128
#define NSM     148
#define GRID    (NSM * 4)    // 592 CTAs, 4 per SM (bid % 148 -> same SM)
#define NTILES  (N_PTS / THREADS)      // 1024 tiles of 128 points
#define SM_HI   (NTILES - 6 * NSM)     // 136 SMs own 7 tiles, the rest 6

__device__ float        g_partials[GRID];
__device__ unsigned int g_done = 0;

__device__ __forceinline__ unsigned long long fma2(
    unsigned long long a, unsigned long long b, unsigned long long c) {
    unsigned long long d;
    asm("fma.rn.f32x2 %0, %1, %2, %3;" : "=l"(d) : "l"(a), "l"(b), "l"(c));
    return d;
}
__device__ __forceinline__ unsigned long long dup2(float v) {
    unsigned long long r;
    asm("mov.b64 %0, {%1, %1};" : "=l"(r) : "f"(v));
    return r;
}
__device__ __forceinline__ void unpack2(unsigned long long v, float& lo, float& hi) {
    asm("mov.b64 {%0, %1}, %2;" : "=f"(lo), "=f"(hi) : "l"(v));
}

// Bit-exact distance pair for one code-pair row (same FMA order as hot loop).
__device__ __forceinline__ void pair_dists(const ulonglong2* w,
                                           unsigned long long esq,
                                           const unsigned long long* xd,
                                           float& d0, float& d1) {
    ulonglong2 c0 = w[0], c1 = w[1], c2 = w[2], c3 = w[3], c4 = w[4];
    unsigned long long a = esq;
    a = fma2(c0.x, xd[0], a);
    a = fma2(c0.y, xd[1], a);
    a = fma2(c1.x, xd[2], a);
    a = fma2(c1.y, xd[3], a);
    a = fma2(c2.x, xd[4], a);
    a = fma2(c2.y, xd[5], a);
    a = fma2(c3.x, xd[6], a);
    a = fma2(c3.y, xd[7], a);
    a = fma2(c4.x, xd[8], a);
    a = fma2(c4.y, xd[9], a);
    unpack2(a, d0, d1);
}

// Scan all code pairs for PPT points (one per consecutive tile), write outputs,
// return loss partial.
template <int PPT>
__device__ __forceinline__ float scan_points(
    const float* __restrict__ x, float* __restrict__ out,
    const float* sE, const float* sEsq, int tile0, int tid)
{
    int n[PPT];
    #pragma unroll
    for (int q = 0; q < PPT; q++)
        n[q] = (tile0 + q) * THREADS + tid;

    unsigned long long xd[PPT][D_DIM];
    #pragma unroll
    for (int q = 0; q < PPT; q++) {
        const float* xp = x + (size_t)n[q] * D_DIM;
        #pragma unroll
        for (int j = 0; j < D_DIM; j++)
            xd[q][j] = dup2(-2.f * xp[j]);
    }

    float best[PPT];
    int   bp[PPT];
    #pragma unroll
    for (int q = 0; q < PPT; q++) { best[q] = 3.402823466e+38f; bp[q] = 0; }

    const ulonglong2* dims = (const ulonglong2*)sE;          // 5 per pair row
    const unsigned long long* esqp = (const unsigned long long*)sEsq;

    // software-pipelined: prime pair 0
    ulonglong2 c0 = dims[0], c1 = dims[1], c2 = dims[2], c3 = dims[3], c4 = dims[4];
    unsigned long long esq = esqp[0];

    for (int p = 0; p < NPAIR; ++p) {
        const int pn = (p + 1) & (NPAIR - 1);
        const ulonglong2* wn = dims + (size_t)pn * 5;
        ulonglong2 n0 = wn[0], n1 = wn[1], n2 = wn[2], n3 = wn[3], n4 = wn[4];
        unsigned long long esqn = esqp[pn];

        #pragma unroll
        for (int q = 0; q < PPT; q++) {
            unsigned long long a = esq;
            a = fma2(c0.x, xd[q][0], a);
            a = fma2(c0.y, xd[q][1], a);
            a = fma2(c1.x, xd[q][2], a);
            a = fma2(c1.y, xd[q][3], a);
            a = fma2(c2.x, xd[q][4], a);
            a = fma2(c2.y, xd[q][5], a);
            a = fma2(c3.x, xd[q][6], a);
            a = fma2(c3.y, xd[q][7], a);
            a = fma2(c4.x, xd[q][8], a);
            a = fma2(c4.y, xd[q][9], a);
            float d0, d1;
            unpack2(a, d0, d1);
            float m = fminf(d0, d1);                   // FMNMX (alu pipe)
            if (m < best[q]) { best[q] = m; bp[q] = p; }   // strict < = first min
        }
        c0 = n0; c1 = n1; c2 = n2; c3 = n3; c4 = n4; esq = esqn;
    }

    // resolve winning lane (bit-exact recompute), write out + loss
    float part = 0.f;
    #pragma unroll
    for (int q = 0; q < PPT; q++) {
        int p = bp[q];
        float d0, d1;
        pair_dists(dims + (size_t)p * 5, esqp[p], xd[q], d0, d1);
        int lane = (d1 < d0) ? 1 : 0;                  // tie -> lane 0 (lower k)
        const float* er = sE + p * PROW;
        float* o = out + (size_t)n[q] * D_DIM;
        #pragma unroll
        for (int j = 0; j < D_DIM; j++) {
            float qv = er[2 * j + lane];
            o[j] = qv;
            float lo, hi;
            unpack2(xd[q][j], lo, hi);
            float xv = -0.5f * lo;                     // exact: (-0.5)*(-2x) = x
            float dd = xv - qv;
            part += dd * dd;
        }
    }
    return part;
}

__global__ void __launch_bounds__(THREADS, 4)
vq_kernel(const float* __restrict__ x,      // [N, D]
          const float* __restrict__ E,      // [K, D]
          float* __restrict__ out)          // [N*D] quantized + loss slot
{
    __shared__ float sE[NPAIR * PROW];      // 40960 B: pair-packed dims (f32x2 layout)
    __shared__ float sEsq[K_CB];            //  4096 B: (esq0,esq1) adjacent pairs
    __shared__ float sred[THREADS / 32];
    __shared__ int   s_last;

    const int tid = threadIdx.x;
    const int bid = blockIdx.x;

    // --- codebook -> pair-packed shared: sE[p*20 + 2j + l] = E[(2p+l)*10 + j] ---
    for (int i = tid; i < K_CB * D_DIM; i += THREADS) {
        int k = i / D_DIM;
        int j = i - k * D_DIM;
        sE[(k >> 1) * PROW + 2 * j + (k & 1)] = E[i];
    }
    __syncthreads();
    for (int k = tid; k < K_CB; k += THREADS) {
        int p = k >> 1, l = k & 1;
        float s = 0.f;
        #pragma unroll
        for (int j = 0; j < D_DIM; j++) {
            float v = sE[p * PROW + 2 * j + l];
            s += v * v;
        }
        sEsq[k] = s;
    }
    __syncthreads();

    // --- per-SM balanced tile assignment ---
    // bids congruent mod 148 share an SM (classic-launch LUT[bid % 148]).
    // SM group sg < SM_HI owns 7 tiles, else 6.
    // Slot tile counts: T=7 -> [2,2,2,1], T=6 -> [2,2,1,1].
    const int sg   = bid % NSM;           // SM group id
    const int slot = bid / NSM;           // 0..3
    const int T    = (sg < SM_HI) ? 7 : 6;
    const int smbase = (sg < SM_HI) ? (7 * sg) : (7 * SM_HI + 6 * (sg - SM_HI));
    int cnt, off;
    if (T == 7) { cnt = (slot < 3) ? 2 : 1; off = (slot < 3) ? 2 * slot : 6; }
    else        { cnt = (slot < 2) ? 2 : 1; off = (slot < 2) ? 2 * slot : (4 + (slot - 2)); }
    const int tile0 = smbase + off;

    float part;
    if (cnt == 2)
        part = scan_points<2>(x, out, sE, sEsq, tile0, tid);
    else
        part = scan_points<1>(x, out, sE, sEsq, tile0, tid);

    // --- deterministic loss: warp reduce -> CTA reduce -> per-CTA partial ---
    #pragma unroll
    for (int offr = 16; offr > 0; offr >>= 1)
        part += __shfl_down_sync(0xFFFFFFFFu, part, offr);
    if ((tid & 31) == 0) sred[tid >> 5] = part;
    __syncthreads();

    if (tid == 0) {
        float s = sred[0] + sred[1] + sred[2] + sred[3];
        g_partials[bid] = s;
        __threadfence();
        unsigned int old = atomicAdd(&g_done, 1u);
        s_last = (old == GRID - 1) ? 1 : 0;
    }
    __syncthreads();

    // --- last CTA finalizes loss (fixed order -> deterministic) ---
    if (s_last) {
        __shared__ float sfin[THREADS];
        float s = 0.f;
        for (int r = tid; r < GRID; r += THREADS)   // fixed strided order
            s += g_partials[r];
        sfin[tid] = s;
        __syncthreads();
        #pragma unroll
        for (int o = THREADS / 2; o > 0; o >>= 1) {
            if (tid < o) sfin[tid] += sfin[tid + o];
            __syncthreads();
        }
        if (tid == 0) {
            out[(size_t)N_PTS * D_DIM] = sfin[0] * (1.0f / ((float)N_PTS * (float)D_DIM));
            g_done = 0;   // reset for next graph replay
        }
    }
}

extern "C" void kernel_launch(void* const* d_in, const int* in_sizes, int n_in,
                              void* d_out, int out_size) {
    const float* x = (const float*)d_in[0];   // encoder_embedding [N, D]
    const float* E = (const float*)d_in[1];   // embedding_weight  [K, D]
    float* out = (float*)d_out;

    vq_kernel<<<GRID, THREADS>>>(x, E, out);
}

// round 10
// speedup vs baseline: 1.1429x; 1.1429x over previous
#include <cuda_runtime.h>

#define N_PTS   131072
#define K_CB    1024
#define NPAIR   512          // K_CB / 2
#define D_DIM   10
#define PROW    20           // floats per code-pair row: 10 dims x f32x2
#define THREADS 128
#define GRID    148          // 1 CTA per SM
#define WARPS   (GRID * 4)   // 592 warp-scans
#define WTILES  (N_PTS / 32) // 4096 warp-tiles of 32 points
#define W7      (WTILES - 6 * WARPS)   // 544 warps take 7 tiles, rest take 6

__device__ float        g_partials[GRID];
__device__ unsigned int g_done = 0;

__device__ __forceinline__ unsigned long long fma2(
    unsigned long long a, unsigned long long b, unsigned long long c) {
    unsigned long long d;
    asm("fma.rn.f32x2 %0, %1, %2, %3;" : "=l"(d) : "l"(a), "l"(b), "l"(c));
    return d;
}
__device__ __forceinline__ unsigned long long dup2(float v) {
    unsigned long long r;
    asm("mov.b64 %0, {%1, %1};" : "=l"(r) : "f"(v));
    return r;
}
__device__ __forceinline__ void unpack2(unsigned long long v, float& lo, float& hi) {
    asm("mov.b64 {%0, %1}, %2;" : "=f"(lo), "=f"(hi) : "l"(v));
}

// Bit-exact distance pair for one code-pair row (same FMA order as hot loop).
__device__ __forceinline__ void pair_dists(const ulonglong2* w,
                                           unsigned long long esq,
                                           const unsigned long long* xd,
                                           float& d0, float& d1) {
    ulonglong2 c0 = w[0], c1 = w[1], c2 = w[2], c3 = w[3], c4 = w[4];
    unsigned long long a = esq;
    a = fma2(c0.x, xd[0], a);
    a = fma2(c0.y, xd[1], a);
    a = fma2(c1.x, xd[2], a);
    a = fma2(c1.y, xd[3], a);
    a = fma2(c2.x, xd[4], a);
    a = fma2(c2.y, xd[5], a);
    a = fma2(c3.x, xd[6], a);
    a = fma2(c3.y, xd[7], a);
    a = fma2(c4.x, xd[8], a);
    a = fma2(c4.y, xd[9], a);
    unpack2(a, d0, d1);
}

// Scan all code pairs for PPT warp-tiles (this lane handles one point per tile).
template <int PPT>
__device__ __forceinline__ float scan_points(
    const float* __restrict__ x, float* __restrict__ out,
    const float* sE, const float* sEsq, int wt0, int lane)
{
    int n[PPT];
    #pragma unroll
    for (int q = 0; q < PPT; q++)
        n[q] = (wt0 + q) * 32 + lane;

    unsigned long long xd[PPT][D_DIM];
    #pragma unroll
    for (int q = 0; q < PPT; q++) {
        const float* xp = x + (size_t)n[q] * D_DIM;
        #pragma unroll
        for (int j = 0; j < D_DIM; j++)
            xd[q][j] = dup2(-2.f * xp[j]);
    }

    float best[PPT];
    int   bp[PPT];
    #pragma unroll
    for (int q = 0; q < PPT; q++) { best[q] = 3.402823466e+38f; bp[q] = 0; }

    const ulonglong2* dims = (const ulonglong2*)sE;          // 5 per pair row
    const unsigned long long* esqp = (const unsigned long long*)sEsq;

    // software-pipelined: prime pair 0
    ulonglong2 c0 = dims[0], c1 = dims[1], c2 = dims[2], c3 = dims[3], c4 = dims[4];
    unsigned long long esq = esqp[0];

    for (int p = 0; p < NPAIR; ++p) {
        const int pn = (p + 1) & (NPAIR - 1);
        const ulonglong2* wn = dims + (size_t)pn * 5;
        ulonglong2 n0 = wn[0], n1 = wn[1], n2 = wn[2], n3 = wn[3], n4 = wn[4];
        unsigned long long esqn = esqp[pn];

        #pragma unroll
        for (int q = 0; q < PPT; q++) {
            unsigned long long a = esq;
            a = fma2(c0.x, xd[q][0], a);
            a = fma2(c0.y, xd[q][1], a);
            a = fma2(c1.x, xd[q][2], a);
            a = fma2(c1.y, xd[q][3], a);
            a = fma2(c2.x, xd[q][4], a);
            a = fma2(c2.y, xd[q][5], a);
            a = fma2(c3.x, xd[q][6], a);
            a = fma2(c3.y, xd[q][7], a);
            a = fma2(c4.x, xd[q][8], a);
            a = fma2(c4.y, xd[q][9], a);
            float d0, d1;
            unpack2(a, d0, d1);
            float m = fminf(d0, d1);                   // FMNMX (alu pipe)
            if (m < best[q]) { best[q] = m; bp[q] = p; }   // strict < = first min
        }
        c0 = n0; c1 = n1; c2 = n2; c3 = n3; c4 = n4; esq = esqn;
    }

    // resolve winning lane (bit-exact recompute), write out + loss
    float part = 0.f;
    #pragma unroll
    for (int q = 0; q < PPT; q++) {
        int p = bp[q];
        float d0, d1;
        pair_dists(dims + (size_t)p * 5, esqp[p], xd[q], d0, d1);
        int lsel = (d1 < d0) ? 1 : 0;                  // tie -> lane 0 (lower k)
        const float* er = sE + p * PROW;
        float* o = out + (size_t)n[q] * D_DIM;
        #pragma unroll
        for (int j = 0; j < D_DIM; j++) {
            float qv = er[2 * j + lsel];
            o[j] = qv;
            float lo, hi;
            unpack2(xd[q][j], lo, hi);
            float xv = -0.5f * lo;                     // exact: (-0.5)*(-2x) = x
            float dd = xv - qv;
            part += dd * dd;
        }
    }
    return part;
}

__global__ void __launch_bounds__(THREADS, 1)
vq_kernel(const float* __restrict__ x,      // [N, D]
          const float* __restrict__ E,      // [K, D]
          float* __restrict__ out)          // [N*D] quantized + loss slot
{
    __shared__ float sE[NPAIR * PROW];      // 40960 B: pair-packed dims (f32x2 layout)
    __shared__ float sEsq[K_CB];            //  4096 B: (esq0,esq1) adjacent pairs
    __shared__ float sred[THREADS / 32];
    __shared__ int   s_last;

    const int tid  = threadIdx.x;
    const int bid  = blockIdx.x;
    const int wid  = tid >> 5;              // 0..3 -> all 4 SMSPs
    const int lane = tid & 31;

    // --- codebook -> pair-packed shared: sE[p*20 + 2j + l] = E[(2p+l)*10 + j] ---
    for (int i = tid; i < K_CB * D_DIM; i += THREADS) {
        int k = i / D_DIM;
        int j = i - k * D_DIM;
        sE[(k >> 1) * PROW + 2 * j + (k & 1)] = E[i];
    }
    __syncthreads();
    for (int k = tid; k < K_CB; k += THREADS) {
        int p = k >> 1, l = k & 1;
        float s = 0.f;
        #pragma unroll
        for (int j = 0; j < D_DIM; j++) {
            float v = sE[p * PROW + 2 * j + l];
            s += v * v;
        }
        sEsq[k] = s;
    }
    __syncthreads();

    // --- per-warp balanced tile assignment ---
    // global warp id g in [0, 592): g < W7 -> 7 warp-tiles, else 6.
    const int g = bid * 4 + wid;
    int wt0, cnt;
    if (g < W7) { cnt = 7; wt0 = g * 7; }
    else        { cnt = 6; wt0 = W7 * 7 + (g - W7) * 6; }

    float part;
    if (cnt == 7)
        part = scan_points<7>(x, out, sE, sEsq, wt0, lane);
    else
        part = scan_points<6>(x, out, sE, sEsq, wt0, lane);

    // --- deterministic loss: warp reduce -> CTA reduce -> per-CTA partial ---
    #pragma unroll
    for (int offr = 16; offr > 0; offr >>= 1)
        part += __shfl_down_sync(0xFFFFFFFFu, part, offr);
    if (lane == 0) sred[wid] = part;
    __syncthreads();

    if (tid == 0) {
        float s = sred[0] + sred[1] + sred[2] + sred[3];
        g_partials[bid] = s;
        __threadfence();
        unsigned int old = atomicAdd(&g_done, 1u);
        s_last = (old == GRID - 1) ? 1 : 0;
    }
    __syncthreads();

    // --- last CTA finalizes loss (fixed order -> deterministic) ---
    if (s_last) {
        __shared__ float sfin[THREADS];
        float s = 0.f;
        for (int r = tid; r < GRID; r += THREADS)   // fixed strided order
            s += g_partials[r];
        sfin[tid] = s;
        __syncthreads();
        #pragma unroll
        for (int o = THREADS / 2; o > 0; o >>= 1) {
            if (tid < o) sfin[tid] += sfin[tid + o];
            __syncthreads();
        }
        if (tid == 0) {
            out[(size_t)N_PTS * D_DIM] = sfin[0] * (1.0f / ((float)N_PTS * (float)D_DIM));
            g_done = 0;   // reset for next graph replay
        }
    }
}

extern "C" void kernel_launch(void* const* d_in, const int* in_sizes, int n_in,
                              void* d_out, int out_size) {
    const float* x = (const float*)d_in[0];   // encoder_embedding [N, D]
    const float* E = (const float*)d_in[1];   // embedding_weight  [K, D]
    float* out = (float*)d_out;

    vq_kernel<<<GRID, THREADS>>>(x, E, out);
}

// round 11
// speedup vs baseline: 1.1712x; 1.0248x over previous
#include <cuda_runtime.h>

#define N_PTS   131072
#define K_CB    1024
#define NPAIR   512          // K_CB / 2
#define D_DIM   10
#define PROW    20           // floats per code-pair row: 10 dims x f32x2
#define THREADS 128
#define NSM     148
#define GRID    (NSM * 2)    // 296 CTAs: 2 per SM, 2 warps per SMSP
#define WARPS   (GRID * 4)   // 1184 warp-scans
#define WTILES  (N_PTS / 32) // 4096 warp-tiles of 32 points
#define W4      (WTILES - 3 * WARPS)   // 544 warps take 4 tiles, rest take 3

__device__ float        g_partials[GRID];
__device__ unsigned int g_done = 0;

__device__ __forceinline__ unsigned long long fma2(
    unsigned long long a, unsigned long long b, unsigned long long c) {
    unsigned long long d;
    asm("fma.rn.f32x2 %0, %1, %2, %3;" : "=l"(d) : "l"(a), "l"(b), "l"(c));
    return d;
}
__device__ __forceinline__ unsigned long long dup2(float v) {
    unsigned long long r;
    asm("mov.b64 %0, {%1, %1};" : "=l"(r) : "f"(v));
    return r;
}
__device__ __forceinline__ void unpack2(unsigned long long v, float& lo, float& hi) {
    asm("mov.b64 {%0, %1}, %2;" : "=f"(lo), "=f"(hi) : "l"(v));
}

// Bit-exact distance pair for one code-pair row (same FMA order as hot loop).
__device__ __forceinline__ void pair_dists(const ulonglong2* w,
                                           unsigned long long esq,
                                           const unsigned long long* xd,
                                           float& d0, float& d1) {
    ulonglong2 c0 = w[0], c1 = w[1], c2 = w[2], c3 = w[3], c4 = w[4];
    unsigned long long a = esq;
    a = fma2(c0.x, xd[0], a);
    a = fma2(c0.y, xd[1], a);
    a = fma2(c1.x, xd[2], a);
    a = fma2(c1.y, xd[3], a);
    a = fma2(c2.x, xd[4], a);
    a = fma2(c2.y, xd[5], a);
    a = fma2(c3.x, xd[6], a);
    a = fma2(c3.y, xd[7], a);
    a = fma2(c4.x, xd[8], a);
    a = fma2(c4.y, xd[9], a);
    unpack2(a, d0, d1);
}

// Scan all code pairs for PPT warp-tiles (this lane handles one point per tile).
template <int PPT>
__device__ __forceinline__ float scan_points(
    const float* __restrict__ x, float* __restrict__ out,
    const float* sE, const float* sEsq, int wt0, int lane)
{
    int n[PPT];
    #pragma unroll
    for (int q = 0; q < PPT; q++)
        n[q] = (wt0 + q) * 32 + lane;

    unsigned long long xd[PPT][D_DIM];
    #pragma unroll
    for (int q = 0; q < PPT; q++) {
        const float* xp = x + (size_t)n[q] * D_DIM;
        #pragma unroll
        for (int j = 0; j < D_DIM; j++)
            xd[q][j] = dup2(-2.f * xp[j]);
    }

    float best[PPT];
    int   bp[PPT];
    #pragma unroll
    for (int q = 0; q < PPT; q++) { best[q] = 3.402823466e+38f; bp[q] = 0; }

    const ulonglong2* dims = (const ulonglong2*)sE;          // 5 per pair row
    const unsigned long long* esqp = (const unsigned long long*)sEsq;

    // software-pipelined: prime pair 0
    ulonglong2 c0 = dims[0], c1 = dims[1], c2 = dims[2], c3 = dims[3], c4 = dims[4];
    unsigned long long esq = esqp[0];

    for (int p = 0; p < NPAIR; ++p) {
        const int pn = (p + 1) & (NPAIR - 1);
        const ulonglong2* wn = dims + (size_t)pn * 5;
        ulonglong2 n0 = wn[0], n1 = wn[1], n2 = wn[2], n3 = wn[3], n4 = wn[4];
        unsigned long long esqn = esqp[pn];

        #pragma unroll
        for (int q = 0; q < PPT; q++) {
            unsigned long long a = esq;
            a = fma2(c0.x, xd[q][0], a);
            a = fma2(c0.y, xd[q][1], a);
            a = fma2(c1.x, xd[q][2], a);
            a = fma2(c1.y, xd[q][3], a);
            a = fma2(c2.x, xd[q][4], a);
            a = fma2(c2.y, xd[q][5], a);
            a = fma2(c3.x, xd[q][6], a);
            a = fma2(c3.y, xd[q][7], a);
            a = fma2(c4.x, xd[q][8], a);
            a = fma2(c4.y, xd[q][9], a);
            float d0, d1;
            unpack2(a, d0, d1);
            float m = fminf(d0, d1);                   // FMNMX (alu pipe)
            if (m < best[q]) { best[q] = m; bp[q] = p; }   // strict < = first min
        }
        c0 = n0; c1 = n1; c2 = n2; c3 = n3; c4 = n4; esq = esqn;
    }

    // resolve winning lane (bit-exact recompute), write out + loss
    float part = 0.f;
    #pragma unroll
    for (int q = 0; q < PPT; q++) {
        int p = bp[q];
        float d0, d1;
        pair_dists(dims + (size_t)p * 5, esqp[p], xd[q], d0, d1);
        int lsel = (d1 < d0) ? 1 : 0;                  // tie -> lane 0 (lower k)
        const float* er = sE + p * PROW;
        float* o = out + (size_t)n[q] * D_DIM;
        #pragma unroll
        for (int j = 0; j < D_DIM; j++) {
            float qv = er[2 * j + lsel];
            o[j] = qv;
            float lo, hi;
            unpack2(xd[q][j], lo, hi);
            float xv = -0.5f * lo;                     // exact: (-0.5)*(-2x) = x
            float dd = xv - qv;
            part += dd * dd;
        }
    }
    return part;
}

__global__ void __launch_bounds__(THREADS, 2)
vq_kernel(const float* __restrict__ x,      // [N, D]
          const float* __restrict__ E,      // [K, D]
          float* __restrict__ out)          // [N*D] quantized + loss slot
{
    __shared__ float sE[NPAIR * PROW];      // 40960 B: pair-packed dims (f32x2 layout)
    __shared__ float sEsq[K_CB];            //  4096 B: (esq0,esq1) adjacent pairs
    __shared__ float sred[THREADS / 32];
    __shared__ int   s_last;

    const int tid  = threadIdx.x;
    const int bid  = blockIdx.x;
    const int wid  = tid >> 5;              // 0..3 -> all 4 SMSPs
    const int lane = tid & 31;

    // --- codebook -> pair-packed shared: sE[p*20 + 2j + l] = E[(2p+l)*10 + j] ---
    for (int i = tid; i < K_CB * D_DIM; i += THREADS) {
        int k = i / D_DIM;
        int j = i - k * D_DIM;
        sE[(k >> 1) * PROW + 2 * j + (k & 1)] = E[i];
    }
    __syncthreads();
    for (int k = tid; k < K_CB; k += THREADS) {
        int p = k >> 1, l = k & 1;
        float s = 0.f;
        #pragma unroll
        for (int j = 0; j < D_DIM; j++) {
            float v = sE[p * PROW + 2 * j + l];
            s += v * v;
        }
        sEsq[k] = s;
    }
    __syncthreads();

    // --- per-warp balanced tile assignment ---
    // global warp id g in [0, 1184): g < W4 -> 4 warp-tiles, else 3.
    const int g = bid * 4 + wid;
    int wt0, cnt;
    if (g < W4) { cnt = 4; wt0 = g * 4; }
    else        { cnt = 3; wt0 = W4 * 4 + (g - W4) * 3; }

    float part;
    if (cnt == 4)
        part = scan_points<4>(x, out, sE, sEsq, wt0, lane);
    else
        part = scan_points<3>(x, out, sE, sEsq, wt0, lane);

    // --- deterministic loss: warp reduce -> CTA reduce -> per-CTA partial ---
    #pragma unroll
    for (int offr = 16; offr > 0; offr >>= 1)
        part += __shfl_down_sync(0xFFFFFFFFu, part, offr);
    if (lane == 0) sred[wid] = part;
    __syncthreads();

    if (tid == 0) {
        float s = sred[0] + sred[1] + sred[2] + sred[3];
        g_partials[bid] = s;
        __threadfence();
        unsigned int old = atomicAdd(&g_done, 1u);
        s_last = (old == GRID - 1) ? 1 : 0;
    }
    __syncthreads();

    // --- last CTA finalizes loss (fixed order -> deterministic) ---
    if (s_last) {
        __shared__ float sfin[THREADS];
        float s = 0.f;
        for (int r = tid; r < GRID; r += THREADS)   // fixed strided order
            s += g_partials[r];
        sfin[tid] = s;
        __syncthreads();
        #pragma unroll
        for (int o = THREADS / 2; o > 0; o >>= 1) {
            if (tid < o) sfin[tid] += sfin[tid + o];
            __syncthreads();
        }
        if (tid == 0) {
            out[(size_t)N_PTS * D_DIM] = sfin[0] * (1.0f / ((float)N_PTS * (float)D_DIM));
            g_done = 0;   // reset for next graph replay
        }
    }
}

extern "C" void kernel_launch(void* const* d_in, const int* in_sizes, int n_in,
                              void* d_out, int out_size) {
    const float* x = (const float*)d_in[0];   // encoder_embedding [N, D]
    const float* E = (const float*)d_in[1];   // embedding_weight  [K, D]
    float* out = (float*)d_out;

    vq_kernel<<<GRID, THREADS>>>(x, E, out);
}